// round 12
// baseline (speedup 1.0000x reference)
#include <cuda_runtime.h>
#include <cuda_bf16.h>
#include <cstdint>
#include <math.h>

#define CD 256
#define MD 512
#define HWD 4096
#define NIMG 16
#define LAMBDA 0.0025f
#define SROW 514

// SMEM layout (bytes)
#define ATT_LO 0u          // att lo [32 x 1040B] (overlays sc after reg-staged pack)
#define XA_HI  65792u      // x-hat hi [32 x 528B]; later att hi [32 x 1040B]
#define XA_LO  82688u
#define ATT_HI 65792u
#define RED_O  99584u      // 256 f32
#define INV_O  100608u     // 32 f32
#define SMEM_SZ 100736u
#define XLD    16896u      // XA_LO - XA_HI

// B1: [m][kt*4+q] -> uint2 {hi-pair(kt*8+q), hi-pair(kt*8+q+4)}
__device__ uint2 g_B1q[MD*64];
// B2: [c][kt*4+q] -> uint4 {hi(p0), lo(p0), hi(p1), lo(p1)}, p0=kt*8+q, p1=p0+4
__device__ uint4 g_B2q[CD*128];

__device__ __forceinline__ uint32_t smem_u32(const void* p) {
    uint32_t a;
    asm("{ .reg .u64 t; cvta.to.shared.u64 t, %1; cvt.u32.u64 %0, t; }" : "=r"(a) : "l"(p));
    return a;
}
#define LDSM4(r,a) asm volatile("ldmatrix.sync.aligned.m8n8.x4.shared.b16 {%0,%1,%2,%3},[%4];" \
    : "=r"((r)[0]),"=r"((r)[1]),"=r"((r)[2]),"=r"((r)[3]) : "r"(a))
#define MMA(d,a,bb) asm volatile( \
    "mma.sync.aligned.m16n8k16.row.col.f32.bf16.bf16.f32 {%0,%1,%2,%3},{%4,%5,%6,%7},{%8,%9},{%0,%1,%2,%3};" \
    : "+f"((d)[0]),"+f"((d)[1]),"+f"((d)[2]),"+f"((d)[3]) \
    : "r"((a)[0]),"r"((a)[1]),"r"((a)[2]),"r"((a)[3]),"r"((bb)[0]),"r"((bb)[1]))

__device__ __forceinline__ void pack_hl(const float* v, char* hi, char* lo) {
    uint4 h, l;
    float r[8];
#pragma unroll
    for (int j = 0; j < 8; j++)
        r[j] = v[j] - __bfloat162float(__float2bfloat16(v[j]));
    __nv_bfloat162 h0 = __floats2bfloat162_rn(v[0], v[1]), h1 = __floats2bfloat162_rn(v[2], v[3]);
    __nv_bfloat162 h2 = __floats2bfloat162_rn(v[4], v[5]), h3 = __floats2bfloat162_rn(v[6], v[7]);
    __nv_bfloat162 l0 = __floats2bfloat162_rn(r[0], r[1]), l1 = __floats2bfloat162_rn(r[2], r[3]);
    __nv_bfloat162 l2 = __floats2bfloat162_rn(r[4], r[5]), l3 = __floats2bfloat162_rn(r[6], r[7]);
    h.x = *(uint32_t*)&h0; h.y = *(uint32_t*)&h1; h.z = *(uint32_t*)&h2; h.w = *(uint32_t*)&h3;
    l.x = *(uint32_t*)&l0; l.y = *(uint32_t*)&l1; l.z = *(uint32_t*)&l2; l.w = *(uint32_t*)&l3;
    *(uint4*)hi = h; *(uint4*)lo = l;
}

// ------- prologue: MLP for slot PAIR (2P, 2P+1), direct B1q/B2q pack -------
__global__ __launch_bounds__(256)
void mem_mlp_kernel(const float* __restrict__ memory,
                    const float* __restrict__ w1, const float* __restrict__ b1,
                    const float* __restrict__ w2, const float* __restrict__ b2) {
    __shared__ float srow[2][CD];
    __shared__ float part[2][128][2];
    __shared__ float h[2][128];
    __shared__ float scr[2][CD];
    __shared__ float invs[2];
    __shared__ __nv_bfloat16 sh[2][CD], sl[2][CD];
    const int P = blockIdx.x, m0 = P*2, tid = threadIdx.x;
    const int lane = tid & 31, wid = tid >> 5;

    for (int i = tid; i < 2*CD; i += 256)
        srow[i >> 8][i & 255] = memory[(m0 + (i >> 8))*CD + (i & 255)];
    __syncthreads();

    {   // layer1 k-split: unit u, half sums 128 c's, both slots
        const int u = tid & 127, half = tid >> 7;
        float a0 = half ? 0.f : b1[u], a1 = 0.f;
        const int c0 = half*128;
#pragma unroll 8
        for (int c = c0; c < c0 + 128; c++) {
            const float wv = w1[c*128 + u];
            a0 += srow[0][c] * wv;  a1 += srow[1][c] * wv;
        }
        part[0][u][half] = a0;  part[1][u][half] = a1;
    }
    __syncthreads();
    {
        const int s = tid >> 7, u = tid & 127;
        h[s][u] = fmaxf(part[s][u][0] + part[s][u][1], 0.f);
    }
    __syncthreads();

    float a0 = b2[tid], a1 = a0;
#pragma unroll 8
    for (int j = 0; j < 128; j++) {
        const float wv = w2[j*CD + tid];
        a0 += h[0][j] * wv;  a1 += h[1][j] * wv;
    }
    a0 = fmaxf(a0, 0.f);  a1 = fmaxf(a1, 0.f);
    scr[0][tid] = a0*a0;  scr[1][tid] = a1*a1;
    __syncthreads();
    if (wid < 2) {
        float ss = 0.f;
#pragma unroll
        for (int k = 0; k < 8; k++) ss += scr[wid][lane + 32*k];
#pragma unroll
        for (int o = 16; o > 0; o >>= 1) ss += __shfl_xor_sync(0xffffffffu, ss, o);
        if (lane == 0) invs[wid] = 1.f / fmaxf(sqrtf(ss), 1e-12f);
    }
    __syncthreads();
    {
        const float v0 = a0 * invs[0], v1 = a1 * invs[1];
        __nv_bfloat16 h0 = __float2bfloat16(v0), h1 = __float2bfloat16(v1);
        sh[0][tid] = h0;  sl[0][tid] = __float2bfloat16(v0 - __bfloat162float(h0));
        sh[1][tid] = h1;  sl[1][tid] = __float2bfloat16(v1 - __bfloat162float(h1));
    }
    __syncthreads();
    // B1q: 2 slots x 64 words
    if (tid < 128) {
        const int s = tid >> 6, w = tid & 63;
        const int kt = w >> 2, q = w & 3;
        const int c0 = kt*16 + 2*q;
        __nv_bfloat162 hh0, hh1;
        hh0.x = sh[s][c0];     hh0.y = sh[s][c0+1];
        hh1.x = sh[s][c0+8];   hh1.y = sh[s][c0+9];
        g_B1q[(m0+s)*64 + w] = make_uint2(*(uint32_t*)&hh0, *(uint32_t*)&hh1);
    }
    // B2q: this block owns m-pair P -> one uint2 half per c (thread = c)
    {
        const int kt = P >> 3, q = P & 7;
        const int w = kt*4 + (q & 3);
        const uint32_t off = (q >= 4) ? 8u : 0u;
        __nv_bfloat162 hh, ll;
        hh.x = sh[0][tid];  hh.y = sh[1][tid];
        ll.x = sl[0][tid];  ll.y = sl[1][tid];
        *(uint2*)((char*)(g_B2q + tid*128 + w) + off) =
            make_uint2(*(uint32_t*)&hh, *(uint32_t*)&ll);
    }
}

// ---------------- fused HMMA kernel: 32 tok/CTA, 2 CTA/SM ----------------
__global__ __launch_bounds__(256, 2)
void fused_kernel(const float* __restrict__ x, float* __restrict__ out,
                  float* __restrict__ attmap) {
    extern __shared__ char smem[];
    float* sc  = (float*)smem;
    float* red = (float*)(smem + RED_O);
    float* inv = (float*)(smem + INV_O);
    const uint32_t sb = smem_u32(smem);
    const int tid = threadIdx.x, lane = tid & 31, wid = tid >> 5;
    const int b = blockIdx.x;
    const int n = b >> 7;
    const int hw0 = (b & 127) << 5;
    const float* xb = x + (size_t)n*CD*HWD + hw0;

    // GEMM1 B pointers + early prefetch regs
    const uint2* bbase = g_B1q + (size_t)(wid*64 + (lane >> 2))*64 + (lane & 3);
    uint2 qa[4], qb[4];
#define G1LOAD(q, kt, JJ) { _Pragma("unroll") for (int j = 0; j < 4; j++) \
        (q)[j] = bbase[(size_t)((JJ)*4 + j)*512 + (kt)*4]; }

    // ---- stage x tile [256 c][32 t], coalesced ----
    for (int i = tid; i < CD*32; i += 256)
        sc[i] = xb[(size_t)(i >> 5)*HWD + (i & 31)];
    G1LOAD(qa, 0, 0);          // early: independent of smem
    __syncthreads();

    // ---- token L2 norms ----
    {
        const int t = tid & 31, p = tid >> 5;
        float s = 0.f;
        for (int c = p*32; c < p*32 + 32; c++) { float v = sc[c*32 + t]; s += v*v; }
        red[p*32 + t] = s;
    }
    __syncthreads();
    if (tid < 32) {
        float s = 0.f;
        for (int p = 0; p < 8; p++) s += red[p*32 + tid];
        inv[tid] = 1.f / fmaxf(sqrtf(s), 1e-12f);
    }
    __syncthreads();

    // ---- pack x-hat hi/lo tiles [32 t][256 c], rows 528B ----
    for (int i = tid; i < 1024; i += 256) {
        const int t = i >> 5, ch = i & 31;
        const float iv = inv[t];
        float v[8];
#pragma unroll
        for (int j = 0; j < 8; j++) v[j] = sc[(ch*8 + j)*32 + t] * iv;
        pack_hl(v, smem + XA_HI + t*528 + ch*16, smem + XA_LO + t*528 + ch*16);
    }
    __syncthreads();

    // ---- GEMM1: warp = 32 tok x 64 m, K=256, wide pipelined B ----
    {
        const int mg = wid;
        float acc[2][8][4] = {};
        const uint32_t a0 = sb + XA_HI + (lane & 15)*528 + (lane >> 4)*16;
        const uint32_t a1 = a0 + 16*528;
        uint32_t ah0[4], al0[4], ah1[4], al1[4];

#define G1MMA(q, JJ) { _Pragma("unroll") for (int j = 0; j < 4; j++) { \
        uint32_t bh[2] = {(q)[j].x, (q)[j].y}; \
        MMA(acc[0][(JJ)*4+j], ah0, bh); MMA(acc[0][(JJ)*4+j], al0, bh); \
        MMA(acc[1][(JJ)*4+j], ah1, bh); MMA(acc[1][(JJ)*4+j], al1, bh); } }

        for (int kt = 0; kt < 16; kt++) {
            G1LOAD(qb, kt, 1);                         // LDGs first
            LDSM4(ah0, a0 + kt*32); LDSM4(al0, a0 + kt*32 + XLD);
            LDSM4(ah1, a1 + kt*32); LDSM4(al1, a1 + kt*32 + XLD);
            G1MMA(qa, 0);
            if (kt < 15) G1LOAD(qa, kt+1, 0);
            G1MMA(qb, 1);
        }
#pragma unroll
        for (int th = 0; th < 2; th++)
#pragma unroll
            for (int j = 0; j < 8; j++) {
                const int r0 = th*16 + (lane >> 2);
                const int c = mg*64 + j*8 + (lane & 3)*2;
                *(float2*)&sc[r0*SROW + c]     = make_float2(acc[th][j][0], acc[th][j][1]);
                *(float2*)&sc[(r0+8)*SROW + c] = make_float2(acc[th][j][2], acc[th][j][3]);
            }
    }
    __syncthreads();

    // ---- softmax + shrink + L1 renorm (warp -> 4 tokens) ----
    for (int rt = 0; rt < 4; rt++) {
        const int t = wid*4 + rt;
        float* row = sc + t*SROW;
        float e[16], s = 0.f;
#pragma unroll
        for (int k = 0; k < 16; k++) { e[k] = __expf(row[lane + 32*k]); s += e[k]; }
#pragma unroll
        for (int o = 16; o > 0; o >>= 1) s += __shfl_xor_sync(0xffffffffu, s, o);
        const float invs = 1.f / s;
        float as = 0.f;
#pragma unroll
        for (int k = 0; k < 16; k++) { e[k] = fmaxf(e[k]*invs - LAMBDA, 0.f); as += e[k]; }
#pragma unroll
        for (int o = 16; o > 0; o >>= 1) as += __shfl_xor_sync(0xffffffffu, as, o);
        const float inva = 1.f / fmaxf(as, 1e-12f);
#pragma unroll
        for (int k = 0; k < 16; k++) row[lane + 32*k] = e[k] * inva;
    }
    __syncthreads();

    // GEMM2 B pointer + early prefetch
    const uint4* bbase2 = g_B2q + (size_t)(wid*32 + (lane >> 2))*128 + (lane & 3);
    uint4 qa2[2], qb2[2];
#define G2LOAD(q, kt, JJ) { _Pragma("unroll") for (int j = 0; j < 2; j++) \
        (q)[j] = bbase2[(size_t)((JJ)*2 + j)*1024 + (kt)*4]; }

    // ---- attmap write (coalesced along t) + read att into regs ----
    float* amb = attmap + (size_t)n*MD*HWD + hw0;
    for (int i = tid; i < MD*32; i += 256) {
        const int m = i >> 5, t = i & 31;
        amb[(size_t)m*HWD + t] = sc[t*SROW + m];
    }
    G2LOAD(qa2, 0, 0);         // early: independent of att pack
    // reg-staged att pack: thread -> row pt, col block pg (64 floats)
    {
        const int pt = tid & 31, pg = (tid >> 5) * 64;
        float rbuf[64];
#pragma unroll
        for (int j = 0; j < 32; j++)
            *(float2*)&rbuf[2*j] = *(float2*)&sc[pt*SROW + pg + 2*j];
        __syncthreads();
        char* hb = smem + ATT_HI + pt*1040 + pg*2;
        char* lb = smem + ATT_LO + pt*1040 + pg*2;
#pragma unroll
        for (int jg = 0; jg < 8; jg++)
            pack_hl(rbuf + jg*8, hb + jg*16, lb + jg*16);
    }
    __syncthreads();

    // ---- GEMM2: warp = 32 tok x 32 c, K=512, LDSM A + wide pipelined B ----
    float acc2[2][4][4] = {};
    {
        uint32_t ah[2][4], al[2][4];
        const uint32_t ha0 = sb + ATT_HI + (lane & 15)*1040 + (lane >> 4)*16;
        const uint32_t la0 = sb + ATT_LO + (lane & 15)*1040 + (lane >> 4)*16;

#define G2MMA(q, JJ) { _Pragma("unroll") for (int j = 0; j < 2; j++) { \
        uint32_t bh[2] = {(q)[j].x, (q)[j].z}; \
        uint32_t bl[2] = {(q)[j].y, (q)[j].w}; \
        MMA(acc2[0][(JJ)*2+j], ah[0], bh); MMA(acc2[0][(JJ)*2+j], al[0], bh); MMA(acc2[0][(JJ)*2+j], ah[0], bl); \
        MMA(acc2[1][(JJ)*2+j], ah[1], bh); MMA(acc2[1][(JJ)*2+j], al[1], bh); MMA(acc2[1][(JJ)*2+j], ah[1], bl); } }

        for (int kt = 0; kt < 32; kt++) {
            G2LOAD(qb2, kt, 1);                        // LDGs first
            LDSM4(ah[0], ha0 + kt*32);            LDSM4(al[0], la0 + kt*32);
            LDSM4(ah[1], ha0 + 16*1040 + kt*32);  LDSM4(al[1], la0 + 16*1040 + kt*32);
            G2MMA(qa2, 0);
            if (kt < 31) G2LOAD(qa2, kt+1, 0);
            G2MMA(qb2, 1);
        }
    }
    __syncthreads();   // all warps done reading att tiles

    // ---- stage out [32 t][260] (over ATT_LO region), then coalesced write ----
    {
        const int cg = wid;
#pragma unroll
        for (int th = 0; th < 2; th++)
#pragma unroll
            for (int j = 0; j < 4; j++) {
                const int r0 = th*16 + (lane >> 2);
                const int c = cg*32 + j*8 + (lane & 3)*2;
                *(float2*)&sc[r0*260 + c]     = make_float2(acc2[th][j][0], acc2[th][j][1]);
                *(float2*)&sc[(r0+8)*260 + c] = make_float2(acc2[th][j][2], acc2[th][j][3]);
            }
    }
    __syncthreads();
    float* ob = out + (size_t)n*CD*HWD + hw0;
    for (int i = tid; i < CD*32; i += 256) {
        const int c = i >> 5, t = i & 31;
        ob[(size_t)c*HWD + t] = sc[t*260 + c];
    }
}

// ---------------------------------------------------------------------------
extern "C" void kernel_launch(void* const* d_in, const int* in_sizes, int n_in,
                              void* d_out, int out_size) {
    const float* x      = (const float*)d_in[0];
    const float* memory = (const float*)d_in[1];
    const float* w1     = (const float*)d_in[2];
    const float* b1     = (const float*)d_in[3];
    const float* w2     = (const float*)d_in[4];
    const float* b2     = (const float*)d_in[5];

    float* out    = (float*)d_out;
    float* attmap = out + (size_t)NIMG*CD*HWD;

    mem_mlp_kernel<<<256, 256>>>(memory, w1, b1, w2, b2);

    cudaFuncSetAttribute(fused_kernel, cudaFuncAttributeMaxDynamicSharedMemorySize, SMEM_SZ);
    fused_kernel<<<1024, 256, SMEM_SZ>>>(x, out, attmap);
}

// round 13
// speedup vs baseline: 1.1557x; 1.1557x over previous
#include <cuda_runtime.h>
#include <cuda_bf16.h>
#include <cstdint>
#include <math.h>

#define CD 256
#define MD 512
#define HWD 4096
#define NIMG 16
#define LAMBDA 0.0025f
#define SROW 514

// SMEM layout (bytes)
#define ATT_LO 0u          // att lo [32 x 1040B] (overlays sc after reg-staged pack)
#define XA_HI  65792u      // x-hat hi [32 x 528B]; later att hi [32 x 1040B]
#define XA_LO  82688u
#define ATT_HI 65792u
#define RED_O  99584u      // 256 f32
#define INV_O  100608u     // 32 f32
#define SMEM_SZ 100736u
#define XLD    16896u      // XA_LO - XA_HI

// Fragment-major B operands: one warp LDG = 32 contiguous lanes.
// B1f[((mtile*16 + kt)*32 + lane] : uint2 {hi-pair(kt*8+q), hi-pair(kt*8+q+4)},
//     mtile=0..63 (8 m-rows each), m = mtile*8 + (lane>>2), q = lane&3
__device__ uint2 g_B1f[32768];
// B2f[((ctile*32 + kt)*32 + lane] : uint4 {hi(p0),lo(p0),hi(p1),lo(p1)},
//     ctile=0..31, c = ctile*8 + (lane>>2), p0 = kt*8 + (lane&3), p1 = p0+4
__device__ uint4 g_B2f[32768];
__device__ __nv_bfloat16 g_Mh[MD*CD], g_Ml[MD*CD];

__device__ __forceinline__ uint32_t smem_u32(const void* p) {
    uint32_t a;
    asm("{ .reg .u64 t; cvta.to.shared.u64 t, %1; cvt.u32.u64 %0, t; }" : "=r"(a) : "l"(p));
    return a;
}
#define LDSM4(r,a) asm volatile("ldmatrix.sync.aligned.m8n8.x4.shared.b16 {%0,%1,%2,%3},[%4];" \
    : "=r"((r)[0]),"=r"((r)[1]),"=r"((r)[2]),"=r"((r)[3]) : "r"(a))
#define MMA(d,a,bb) asm volatile( \
    "mma.sync.aligned.m16n8k16.row.col.f32.bf16.bf16.f32 {%0,%1,%2,%3},{%4,%5,%6,%7},{%8,%9},{%0,%1,%2,%3};" \
    : "+f"((d)[0]),"+f"((d)[1]),"+f"((d)[2]),"+f"((d)[3]) \
    : "r"((a)[0]),"r"((a)[1]),"r"((a)[2]),"r"((a)[3]),"r"((bb)[0]),"r"((bb)[1]))

__device__ __forceinline__ void pack_hl(const float* v, char* hi, char* lo) {
    uint4 h, l;
    float r[8];
#pragma unroll
    for (int j = 0; j < 8; j++)
        r[j] = v[j] - __bfloat162float(__float2bfloat16(v[j]));
    __nv_bfloat162 h0 = __floats2bfloat162_rn(v[0], v[1]), h1 = __floats2bfloat162_rn(v[2], v[3]);
    __nv_bfloat162 h2 = __floats2bfloat162_rn(v[4], v[5]), h3 = __floats2bfloat162_rn(v[6], v[7]);
    __nv_bfloat162 l0 = __floats2bfloat162_rn(r[0], r[1]), l1 = __floats2bfloat162_rn(r[2], r[3]);
    __nv_bfloat162 l2 = __floats2bfloat162_rn(r[4], r[5]), l3 = __floats2bfloat162_rn(r[6], r[7]);
    h.x = *(uint32_t*)&h0; h.y = *(uint32_t*)&h1; h.z = *(uint32_t*)&h2; h.w = *(uint32_t*)&h3;
    l.x = *(uint32_t*)&l0; l.y = *(uint32_t*)&l1; l.z = *(uint32_t*)&l2; l.w = *(uint32_t*)&l3;
    *(uint4*)hi = h; *(uint4*)lo = l;
}

// ---------------- prologue: MLP (1 slot/block, 512 blocks, k-split L1) ----------------
__global__ __launch_bounds__(256)
void mem_mlp_kernel(const float* __restrict__ memory,
                    const float* __restrict__ w1, const float* __restrict__ b1,
                    const float* __restrict__ w2, const float* __restrict__ b2) {
    __shared__ float srow[CD], part[256], h[128], scr[CD];
    __shared__ float invs_s;
    __shared__ __nv_bfloat16 sh[CD];
    const int m = blockIdx.x, tid = threadIdx.x, lane = tid & 31;

    srow[tid] = memory[m*CD + tid];
    __syncthreads();

    {   // layer1 k-split: u = tid&127, half = tid>>7 sums 128 c's
        const int u = tid & 127, half = tid >> 7;
        float a = half ? 0.f : b1[u];
        const int c0 = half*128;
#pragma unroll 8
        for (int c = c0; c < c0 + 128; c++) a += srow[c] * w1[c*128 + u];
        part[tid] = a;
    }
    __syncthreads();
    if (tid < 128) h[tid] = fmaxf(part[tid] + part[tid + 128], 0.f);
    __syncthreads();

    float a2 = b2[tid];
#pragma unroll 8
    for (int j = 0; j < 128; j++) a2 += h[j] * w2[j*CD + tid];
    a2 = fmaxf(a2, 0.f);
    scr[tid] = a2*a2;
    __syncthreads();
    if (tid < 32) {
        float ss = 0.f;
#pragma unroll
        for (int k = 0; k < 8; k++) ss += scr[tid + 32*k];
#pragma unroll
        for (int o = 16; o > 0; o >>= 1) ss += __shfl_xor_sync(0xffffffffu, ss, o);
        if (lane == 0) invs_s = 1.f / fmaxf(sqrtf(ss), 1e-12f);
    }
    __syncthreads();
    {
        const float v = a2 * invs_s;
        __nv_bfloat16 hb = __float2bfloat16(v);
        g_Mh[m*CD + tid] = hb;
        g_Ml[m*CD + tid] = __float2bfloat16(v - __bfloat162float(hb));
        sh[tid] = hb;
    }
    __syncthreads();
    // B1f fragment-major write: this block owns m -> 64 uint2 entries
    if (tid < 64) {
        const int kt = tid >> 2, q = tid & 3;
        const int c0 = kt*16 + 2*q;
        __nv_bfloat162 hh0, hh1;
        hh0.x = sh[c0];     hh0.y = sh[c0+1];
        hh1.x = sh[c0+8];   hh1.y = sh[c0+9];
        g_B1f[((m >> 3)*16 + kt)*32 + (m & 7)*4 + q] =
            make_uint2(*(uint32_t*)&hh0, *(uint32_t*)&hh1);
    }
}

// B2f pack: flat idx == output index (ct*1024 + kt*32 + lane)
__global__ void pack2_kernel() {
    const int idx = blockIdx.x*256 + threadIdx.x;   // 32768
    const int lane = idx & 31, kt = (idx >> 5) & 31, ct = idx >> 10;
    const int c = ct*8 + (lane >> 2), q = lane & 3;
    const int p0 = kt*8 + q, p1 = p0 + 4;
    __nv_bfloat162 hh0, ll0, hh1, ll1;
    hh0.x = g_Mh[(2*p0)*CD + c];   hh0.y = g_Mh[(2*p0+1)*CD + c];
    ll0.x = g_Ml[(2*p0)*CD + c];   ll0.y = g_Ml[(2*p0+1)*CD + c];
    hh1.x = g_Mh[(2*p1)*CD + c];   hh1.y = g_Mh[(2*p1+1)*CD + c];
    ll1.x = g_Ml[(2*p1)*CD + c];   ll1.y = g_Ml[(2*p1+1)*CD + c];
    g_B2f[idx] = make_uint4(*(uint32_t*)&hh0, *(uint32_t*)&ll0,
                            *(uint32_t*)&hh1, *(uint32_t*)&ll1);
}

// ---------------- fused HMMA kernel: 32 tok/CTA, 2 CTA/SM ----------------
__global__ __launch_bounds__(256, 2)
void fused_kernel(const float* __restrict__ x, float* __restrict__ out,
                  float* __restrict__ attmap) {
    extern __shared__ char smem[];
    float* sc  = (float*)smem;
    float* red = (float*)(smem + RED_O);
    float* inv = (float*)(smem + INV_O);
    const uint32_t sb = smem_u32(smem);
    const int tid = threadIdx.x, lane = tid & 31, wid = tid >> 5;
    const int b = blockIdx.x;
    const int n = b >> 7;
    const int hw0 = (b & 127) << 5;
    const float* xb = x + (size_t)n*CD*HWD + hw0;

    // ---- stage x tile [256 c][32 t], coalesced ----
    for (int i = tid; i < CD*32; i += 256)
        sc[i] = xb[(size_t)(i >> 5)*HWD + (i & 31)];
    __syncthreads();

    // ---- token L2 norms ----
    {
        const int t = tid & 31, p = tid >> 5;
        float s = 0.f;
        for (int c = p*32; c < p*32 + 32; c++) { float v = sc[c*32 + t]; s += v*v; }
        red[p*32 + t] = s;
    }
    __syncthreads();
    if (tid < 32) {
        float s = 0.f;
        for (int p = 0; p < 8; p++) s += red[p*32 + tid];
        inv[tid] = 1.f / fmaxf(sqrtf(s), 1e-12f);
    }
    __syncthreads();

    // ---- pack x-hat hi/lo tiles [32 t][256 c], rows 528B ----
    for (int i = tid; i < 1024; i += 256) {
        const int t = i >> 5, ch = i & 31;
        const float iv = inv[t];
        float v[8];
#pragma unroll
        for (int j = 0; j < 8; j++) v[j] = sc[(ch*8 + j)*32 + t] * iv;
        pack_hl(v, smem + XA_HI + t*528 + ch*16, smem + XA_LO + t*528 + ch*16);
    }
    __syncthreads();

    // ---- GEMM1: warp = 32 tok x 64 m, K=256, fragment-major pipelined B ----
    {
        const int mg = wid;
        float acc[2][8][4] = {};
        const uint32_t a0 = sb + XA_HI + (lane & 15)*528 + (lane >> 4)*16;
        const uint32_t a1 = a0 + 16*528;
        const uint2* b1p = g_B1f + (size_t)mg*8*512 + lane;
        uint2 qa[4], qb[4];
        uint32_t ah0[4], al0[4], ah1[4], al1[4];

#define G1LOAD(q, kt, JJ) { _Pragma("unroll") for (int j = 0; j < 4; j++) \
        (q)[j] = b1p[(size_t)((JJ)*4 + j)*512 + (kt)*32]; }
#define G1MMA(q, JJ) { _Pragma("unroll") for (int j = 0; j < 4; j++) { \
        uint32_t bh[2] = {(q)[j].x, (q)[j].y}; \
        MMA(acc[0][(JJ)*4+j], ah0, bh); MMA(acc[0][(JJ)*4+j], al0, bh); \
        MMA(acc[1][(JJ)*4+j], ah1, bh); MMA(acc[1][(JJ)*4+j], al1, bh); } }

        G1LOAD(qa, 0, 0);
        for (int kt = 0; kt < 16; kt++) {
            LDSM4(ah0, a0 + kt*32); LDSM4(al0, a0 + kt*32 + XLD);
            LDSM4(ah1, a1 + kt*32); LDSM4(al1, a1 + kt*32 + XLD);
            G1LOAD(qb, kt, 1);
            G1MMA(qa, 0);
            if (kt < 15) G1LOAD(qa, kt+1, 0);
            G1MMA(qb, 1);
        }
#pragma unroll
        for (int th = 0; th < 2; th++)
#pragma unroll
            for (int j = 0; j < 8; j++) {
                const int r0 = th*16 + (lane >> 2);
                const int c = mg*64 + j*8 + (lane & 3)*2;
                *(float2*)&sc[r0*SROW + c]     = make_float2(acc[th][j][0], acc[th][j][1]);
                *(float2*)&sc[(r0+8)*SROW + c] = make_float2(acc[th][j][2], acc[th][j][3]);
            }
    }
    __syncthreads();

    // ---- softmax + shrink + L1 renorm (warp -> 4 tokens) ----
    for (int rt = 0; rt < 4; rt++) {
        const int t = wid*4 + rt;
        float* row = sc + t*SROW;
        float e[16], s = 0.f;
#pragma unroll
        for (int k = 0; k < 16; k++) { e[k] = __expf(row[lane + 32*k]); s += e[k]; }
#pragma unroll
        for (int o = 16; o > 0; o >>= 1) s += __shfl_xor_sync(0xffffffffu, s, o);
        const float invs = 1.f / s;
        float as = 0.f;
#pragma unroll
        for (int k = 0; k < 16; k++) { e[k] = fmaxf(e[k]*invs - LAMBDA, 0.f); as += e[k]; }
#pragma unroll
        for (int o = 16; o > 0; o >>= 1) as += __shfl_xor_sync(0xffffffffu, as, o);
        const float inva = 1.f / fmaxf(as, 1e-12f);
#pragma unroll
        for (int k = 0; k < 16; k++) row[lane + 32*k] = e[k] * inva;
    }
    __syncthreads();

    // ---- attmap write (coalesced along t) + read att into regs ----
    float* amb = attmap + (size_t)n*MD*HWD + hw0;
    for (int i = tid; i < MD*32; i += 256) {
        const int m = i >> 5, t = i & 31;
        amb[(size_t)m*HWD + t] = sc[t*SROW + m];
    }
    // reg-staged att pack: thread -> row pt, col block pg (64 floats)
    {
        const int pt = tid & 31, pg = (tid >> 5) * 64;
        float rbuf[64];
#pragma unroll
        for (int j = 0; j < 32; j++)
            *(float2*)&rbuf[2*j] = *(float2*)&sc[pt*SROW + pg + 2*j];
        __syncthreads();
        char* hb = smem + ATT_HI + pt*1040 + pg*2;
        char* lb = smem + ATT_LO + pt*1040 + pg*2;
#pragma unroll
        for (int jg = 0; jg < 8; jg++)
            pack_hl(rbuf + jg*8, hb + jg*16, lb + jg*16);
    }
    __syncthreads();

    // ---- GEMM2: warp = 32 tok x 32 c, K=512, LDSM A + fragment-major B ----
    float acc2[2][4][4] = {};
    {
        const int cg = wid;
        const uint4* b2p = g_B2f + (size_t)cg*4096 + lane;
        uint4 qa2[2], qb2[2];
        uint32_t ah[2][4], al[2][4];
        const uint32_t ha0 = sb + ATT_HI + (lane & 15)*1040 + (lane >> 4)*16;
        const uint32_t la0 = sb + ATT_LO + (lane & 15)*1040 + (lane >> 4)*16;

#define G2LOAD(q, kt, JJ) { _Pragma("unroll") for (int j = 0; j < 2; j++) \
        (q)[j] = b2p[(size_t)((JJ)*2 + j)*1024 + (kt)*32]; }
#define G2MMA(q, JJ) { _Pragma("unroll") for (int j = 0; j < 2; j++) { \
        uint32_t bh[2] = {(q)[j].x, (q)[j].z}; \
        uint32_t bl[2] = {(q)[j].y, (q)[j].w}; \
        MMA(acc2[0][(JJ)*2+j], ah[0], bh); MMA(acc2[0][(JJ)*2+j], al[0], bh); MMA(acc2[0][(JJ)*2+j], ah[0], bl); \
        MMA(acc2[1][(JJ)*2+j], ah[1], bh); MMA(acc2[1][(JJ)*2+j], al[1], bh); MMA(acc2[1][(JJ)*2+j], ah[1], bl); } }

        G2LOAD(qa2, 0, 0);
        for (int kt = 0; kt < 32; kt++) {
            LDSM4(ah[0], ha0 + kt*32);            LDSM4(al[0], la0 + kt*32);
            LDSM4(ah[1], ha0 + 16*1040 + kt*32);  LDSM4(al[1], la0 + 16*1040 + kt*32);
            G2LOAD(qb2, kt, 1);
            G2MMA(qa2, 0);
            if (kt < 31) G2LOAD(qa2, kt+1, 0);
            G2MMA(qb2, 1);
        }
    }
    __syncthreads();   // all warps done reading att tiles

    // ---- stage out [32 t][260] (over ATT_LO region), then coalesced write ----
    {
        const int cg = wid;
#pragma unroll
        for (int th = 0; th < 2; th++)
#pragma unroll
            for (int j = 0; j < 4; j++) {
                const int r0 = th*16 + (lane >> 2);
                const int c = cg*32 + j*8 + (lane & 3)*2;
                *(float2*)&sc[r0*260 + c]     = make_float2(acc2[th][j][0], acc2[th][j][1]);
                *(float2*)&sc[(r0+8)*260 + c] = make_float2(acc2[th][j][2], acc2[th][j][3]);
            }
    }
    __syncthreads();
    float* ob = out + (size_t)n*CD*HWD + hw0;
    for (int i = tid; i < CD*32; i += 256) {
        const int c = i >> 5, t = i & 31;
        ob[(size_t)c*HWD + t] = sc[t*260 + c];
    }
}

// ---------------------------------------------------------------------------
extern "C" void kernel_launch(void* const* d_in, const int* in_sizes, int n_in,
                              void* d_out, int out_size) {
    const float* x      = (const float*)d_in[0];
    const float* memory = (const float*)d_in[1];
    const float* w1     = (const float*)d_in[2];
    const float* b1     = (const float*)d_in[3];
    const float* w2     = (const float*)d_in[4];
    const float* b2     = (const float*)d_in[5];

    float* out    = (float*)d_out;
    float* attmap = out + (size_t)NIMG*CD*HWD;

    mem_mlp_kernel<<<512, 256>>>(memory, w1, b1, w2, b2);
    pack2_kernel<<<128, 256>>>();

    cudaFuncSetAttribute(fused_kernel, cudaFuncAttributeMaxDynamicSharedMemorySize, SMEM_SZ);
    fused_kernel<<<1024, 256, SMEM_SZ>>>(x, out, attmap);
}

// round 14
// speedup vs baseline: 1.2607x; 1.0908x over previous
#include <cuda_runtime.h>
#include <cuda_bf16.h>
#include <cstdint>
#include <math.h>

#define CD 256
#define MD 512
#define HWD 4096
#define NIMG 16
#define LAMBDA 0.0025f
#define SROW 514

// SMEM layout (bytes)
#define ATT_LO 0u          // att lo [32 x 1040B] (overlays sc after reg-staged pack)
#define XA_HI  65792u      // x-hat hi [32 x 528B]; later att hi [32 x 1040B]
#define ATT_HI 65792u
#define RED_O  99584u      // 256 f32
#define INV_O  100608u     // 32 f32
#define SMEM_SZ 100736u

// Fragment-major B operands: one warp LDG = 32 contiguous lanes.
__device__ uint2 g_B1f[32768];   // [((mtile*16+kt)*32+lane] hi pairs
__device__ uint4 g_B2f[32768];   // [((ctile*32+kt)*32+lane] {hi,lo,hi,lo}
__device__ __nv_bfloat16 g_Mh[MD*CD], g_Ml[MD*CD];

__device__ __forceinline__ uint32_t smem_u32(const void* p) {
    uint32_t a;
    asm("{ .reg .u64 t; cvta.to.shared.u64 t, %1; cvt.u32.u64 %0, t; }" : "=r"(a) : "l"(p));
    return a;
}
#define LDSM4(r,a) asm volatile("ldmatrix.sync.aligned.m8n8.x4.shared.b16 {%0,%1,%2,%3},[%4];" \
    : "=r"((r)[0]),"=r"((r)[1]),"=r"((r)[2]),"=r"((r)[3]) : "r"(a))
#define MMA(d,a,bb) asm volatile( \
    "mma.sync.aligned.m16n8k16.row.col.f32.bf16.bf16.f32 {%0,%1,%2,%3},{%4,%5,%6,%7},{%8,%9},{%0,%1,%2,%3};" \
    : "+f"((d)[0]),"+f"((d)[1]),"+f"((d)[2]),"+f"((d)[3]) \
    : "r"((a)[0]),"r"((a)[1]),"r"((a)[2]),"r"((a)[3]),"r"((bb)[0]),"r"((bb)[1]))

__device__ __forceinline__ void pack_h(const float* v, char* hi) {
    uint4 h;
    __nv_bfloat162 h0 = __floats2bfloat162_rn(v[0], v[1]), h1 = __floats2bfloat162_rn(v[2], v[3]);
    __nv_bfloat162 h2 = __floats2bfloat162_rn(v[4], v[5]), h3 = __floats2bfloat162_rn(v[6], v[7]);
    h.x = *(uint32_t*)&h0; h.y = *(uint32_t*)&h1; h.z = *(uint32_t*)&h2; h.w = *(uint32_t*)&h3;
    *(uint4*)hi = h;
}
__device__ __forceinline__ void pack_hl(const float* v, char* hi, char* lo) {
    uint4 l;
    float r[8];
#pragma unroll
    for (int j = 0; j < 8; j++)
        r[j] = v[j] - __bfloat162float(__float2bfloat16(v[j]));
    pack_h(v, hi);
    __nv_bfloat162 l0 = __floats2bfloat162_rn(r[0], r[1]), l1 = __floats2bfloat162_rn(r[2], r[3]);
    __nv_bfloat162 l2 = __floats2bfloat162_rn(r[4], r[5]), l3 = __floats2bfloat162_rn(r[6], r[7]);
    l.x = *(uint32_t*)&l0; l.y = *(uint32_t*)&l1; l.z = *(uint32_t*)&l2; l.w = *(uint32_t*)&l3;
    *(uint4*)lo = l;
}

// ---------------- prologue: MLP (1 slot/block, 512 blocks, k-split L1) ----------------
__global__ __launch_bounds__(256)
void mem_mlp_kernel(const float* __restrict__ memory,
                    const float* __restrict__ w1, const float* __restrict__ b1,
                    const float* __restrict__ w2, const float* __restrict__ b2) {
    __shared__ float srow[CD], part[256], h[128], scr[CD];
    __shared__ float invs_s;
    __shared__ __nv_bfloat16 sh[CD];
    const int m = blockIdx.x, tid = threadIdx.x, lane = tid & 31;

    srow[tid] = memory[m*CD + tid];
    __syncthreads();

    {   // layer1 k-split: u = tid&127, half = tid>>7 sums 128 c's
        const int u = tid & 127, half = tid >> 7;
        float a = half ? 0.f : b1[u];
        const int c0 = half*128;
#pragma unroll 32
        for (int c = c0; c < c0 + 128; c++) a += srow[c] * w1[c*128 + u];
        part[tid] = a;
    }
    __syncthreads();
    if (tid < 128) h[tid] = fmaxf(part[tid] + part[tid + 128], 0.f);
    __syncthreads();

    float a2 = b2[tid];
#pragma unroll 32
    for (int j = 0; j < 128; j++) a2 += h[j] * w2[j*CD + tid];
    a2 = fmaxf(a2, 0.f);
    scr[tid] = a2*a2;
    __syncthreads();
    if (tid < 32) {
        float ss = 0.f;
#pragma unroll
        for (int k = 0; k < 8; k++) ss += scr[tid + 32*k];
#pragma unroll
        for (int o = 16; o > 0; o >>= 1) ss += __shfl_xor_sync(0xffffffffu, ss, o);
        if (lane == 0) invs_s = 1.f / fmaxf(sqrtf(ss), 1e-12f);
    }
    __syncthreads();
    {
        const float v = a2 * invs_s;
        __nv_bfloat16 hb = __float2bfloat16(v);
        g_Mh[m*CD + tid] = hb;
        g_Ml[m*CD + tid] = __float2bfloat16(v - __bfloat162float(hb));
        sh[tid] = hb;
    }
    __syncthreads();
    if (tid < 64) {
        const int kt = tid >> 2, q = tid & 3;
        const int c0 = kt*16 + 2*q;
        __nv_bfloat162 hh0, hh1;
        hh0.x = sh[c0];     hh0.y = sh[c0+1];
        hh1.x = sh[c0+8];   hh1.y = sh[c0+9];
        g_B1f[((m >> 3)*16 + kt)*32 + (m & 7)*4 + q] =
            make_uint2(*(uint32_t*)&hh0, *(uint32_t*)&hh1);
    }
}

// B2f pack: flat idx == output index (ct*1024 + kt*32 + lane)
__global__ void pack2_kernel() {
    const int idx = blockIdx.x*256 + threadIdx.x;   // 32768
    const int lane = idx & 31, kt = (idx >> 5) & 31, ct = idx >> 10;
    const int c = ct*8 + (lane >> 2), q = lane & 3;
    const int p0 = kt*8 + q, p1 = p0 + 4;
    __nv_bfloat162 hh0, ll0, hh1, ll1;
    hh0.x = g_Mh[(2*p0)*CD + c];   hh0.y = g_Mh[(2*p0+1)*CD + c];
    ll0.x = g_Ml[(2*p0)*CD + c];   ll0.y = g_Ml[(2*p0+1)*CD + c];
    hh1.x = g_Mh[(2*p1)*CD + c];   hh1.y = g_Mh[(2*p1+1)*CD + c];
    ll1.x = g_Ml[(2*p1)*CD + c];   ll1.y = g_Ml[(2*p1+1)*CD + c];
    g_B2f[idx] = make_uint4(*(uint32_t*)&hh0, *(uint32_t*)&ll0,
                            *(uint32_t*)&hh1, *(uint32_t*)&ll1);
}

// ---------------- fused HMMA kernel: 32 tok/CTA, 2 CTA/SM ----------------
__global__ __launch_bounds__(256, 2)
void fused_kernel(const float* __restrict__ x, float* __restrict__ out,
                  float* __restrict__ attmap) {
    extern __shared__ char smem[];
    float* sc  = (float*)smem;
    float* red = (float*)(smem + RED_O);
    float* inv = (float*)(smem + INV_O);
    const uint32_t sb = smem_u32(smem);
    const int tid = threadIdx.x, lane = tid & 31, wid = tid >> 5;
    const int b = blockIdx.x;
    const int n = b >> 7;
    const int hw0 = (b & 127) << 5;
    const float* xb = x + (size_t)n*CD*HWD + hw0;

    // ---- stage x tile [256 c][32 t], coalesced ----
    for (int i = tid; i < CD*32; i += 256)
        sc[i] = xb[(size_t)(i >> 5)*HWD + (i & 31)];
    __syncthreads();

    // ---- token L2 norms ----
    {
        const int t = tid & 31, p = tid >> 5;
        float s = 0.f;
        for (int c = p*32; c < p*32 + 32; c++) { float v = sc[c*32 + t]; s += v*v; }
        red[p*32 + t] = s;
    }
    __syncthreads();
    if (tid < 32) {
        float s = 0.f;
        for (int p = 0; p < 8; p++) s += red[p*32 + tid];
        inv[tid] = 1.f / fmaxf(sqrtf(s), 1e-12f);
    }
    __syncthreads();

    // ---- pack x-hat hi tile [32 t][256 c], rows 528B (hi only) ----
    for (int i = tid; i < 1024; i += 256) {
        const int t = i >> 5, ch = i & 31;
        const float iv = inv[t];
        float v[8];
#pragma unroll
        for (int j = 0; j < 8; j++) v[j] = sc[(ch*8 + j)*32 + t] * iv;
        pack_h(v, smem + XA_HI + t*528 + ch*16);
    }
    __syncthreads();

    // ---- GEMM1: warp = 32 tok x 64 m, K=256, bf16 hi-only ----
    {
        const int mg = wid;
        float acc[2][8][4] = {};
        const uint32_t a0 = sb + XA_HI + (lane & 15)*528 + (lane >> 4)*16;
        const uint32_t a1 = a0 + 16*528;
        const uint2* b1p = g_B1f + (size_t)mg*8*512 + lane;
        uint2 qa[4], qb[4];
        uint32_t ah0[4], ah1[4];

#define G1LOAD(q, kt, JJ) { _Pragma("unroll") for (int j = 0; j < 4; j++) \
        (q)[j] = b1p[(size_t)((JJ)*4 + j)*512 + (kt)*32]; }
#define G1MMA(q, JJ) { _Pragma("unroll") for (int j = 0; j < 4; j++) { \
        uint32_t bh[2] = {(q)[j].x, (q)[j].y}; \
        MMA(acc[0][(JJ)*4+j], ah0, bh); MMA(acc[1][(JJ)*4+j], ah1, bh); } }

        G1LOAD(qa, 0, 0);
        for (int kt = 0; kt < 16; kt++) {
            LDSM4(ah0, a0 + kt*32);
            LDSM4(ah1, a1 + kt*32);
            G1LOAD(qb, kt, 1);
            G1MMA(qa, 0);
            if (kt < 15) G1LOAD(qa, kt+1, 0);
            G1MMA(qb, 1);
        }
#pragma unroll
        for (int th = 0; th < 2; th++)
#pragma unroll
            for (int j = 0; j < 8; j++) {
                const int r0 = th*16 + (lane >> 2);
                const int c = mg*64 + j*8 + (lane & 3)*2;
                *(float2*)&sc[r0*SROW + c]     = make_float2(acc[th][j][0], acc[th][j][1]);
                *(float2*)&sc[(r0+8)*SROW + c] = make_float2(acc[th][j][2], acc[th][j][3]);
            }
    }
    __syncthreads();

    // ---- softmax + shrink + L1 renorm (warp -> 4 tokens) ----
    for (int rt = 0; rt < 4; rt++) {
        const int t = wid*4 + rt;
        float* row = sc + t*SROW;
        float e[16], s = 0.f;
#pragma unroll
        for (int k = 0; k < 16; k++) { e[k] = __expf(row[lane + 32*k]); s += e[k]; }
#pragma unroll
        for (int o = 16; o > 0; o >>= 1) s += __shfl_xor_sync(0xffffffffu, s, o);
        const float invs = 1.f / s;
        float as = 0.f;
#pragma unroll
        for (int k = 0; k < 16; k++) { e[k] = fmaxf(e[k]*invs - LAMBDA, 0.f); as += e[k]; }
#pragma unroll
        for (int o = 16; o > 0; o >>= 1) as += __shfl_xor_sync(0xffffffffu, as, o);
        const float inva = 1.f / fmaxf(as, 1e-12f);
#pragma unroll
        for (int k = 0; k < 16; k++) row[lane + 32*k] = e[k] * inva;
    }
    __syncthreads();

    // ---- attmap write (coalesced along t) + read att into regs ----
    float* amb = attmap + (size_t)n*MD*HWD + hw0;
    for (int i = tid; i < MD*32; i += 256) {
        const int m = i >> 5, t = i & 31;
        amb[(size_t)m*HWD + t] = sc[t*SROW + m];
    }
    // reg-staged att pack: thread -> row pt, col block pg (64 floats)
    {
        const int pt = tid & 31, pg = (tid >> 5) * 64;
        float rbuf[64];
#pragma unroll
        for (int j = 0; j < 32; j++)
            *(float2*)&rbuf[2*j] = *(float2*)&sc[pt*SROW + pg + 2*j];
        __syncthreads();
        char* hb = smem + ATT_HI + pt*1040 + pg*2;
        char* lb = smem + ATT_LO + pt*1040 + pg*2;
#pragma unroll
        for (int jg = 0; jg < 8; jg++)
            pack_hl(rbuf + jg*8, hb + jg*16, lb + jg*16);
    }
    __syncthreads();

    // ---- GEMM2: warp = 32 tok x 32 c, K=512, LDSM A + fragment-major B ----
    float acc2[2][4][4] = {};
    {
        const int cg = wid;
        const uint4* b2p = g_B2f + (size_t)cg*4096 + lane;
        uint4 qa2[2], qb2[2];
        uint32_t ah[2][4], al[2][4];
        const uint32_t ha0 = sb + ATT_HI + (lane & 15)*1040 + (lane >> 4)*16;
        const uint32_t la0 = sb + ATT_LO + (lane & 15)*1040 + (lane >> 4)*16;

#define G2LOAD(q, kt, JJ) { _Pragma("unroll") for (int j = 0; j < 2; j++) \
        (q)[j] = b2p[(size_t)((JJ)*2 + j)*1024 + (kt)*32]; }
#define G2MMA(q, JJ) { _Pragma("unroll") for (int j = 0; j < 2; j++) { \
        uint32_t bh[2] = {(q)[j].x, (q)[j].z}; \
        uint32_t bl[2] = {(q)[j].y, (q)[j].w}; \
        MMA(acc2[0][(JJ)*2+j], ah[0], bh); MMA(acc2[0][(JJ)*2+j], al[0], bh); MMA(acc2[0][(JJ)*2+j], ah[0], bl); \
        MMA(acc2[1][(JJ)*2+j], ah[1], bh); MMA(acc2[1][(JJ)*2+j], al[1], bh); MMA(acc2[1][(JJ)*2+j], ah[1], bl); } }

        G2LOAD(qa2, 0, 0);
        for (int kt = 0; kt < 32; kt++) {
            LDSM4(ah[0], ha0 + kt*32);            LDSM4(al[0], la0 + kt*32);
            LDSM4(ah[1], ha0 + 16*1040 + kt*32);  LDSM4(al[1], la0 + 16*1040 + kt*32);
            G2LOAD(qb2, kt, 1);
            G2MMA(qa2, 0);
            if (kt < 31) G2LOAD(qa2, kt+1, 0);
            G2MMA(qb2, 1);
        }
    }
    __syncthreads();   // all warps done reading att tiles

    // ---- stage out [32 t][260] (over ATT_LO region), then coalesced write ----
    {
        const int cg = wid;
#pragma unroll
        for (int th = 0; th < 2; th++)
#pragma unroll
            for (int j = 0; j < 4; j++) {
                const int r0 = th*16 + (lane >> 2);
                const int c = cg*32 + j*8 + (lane & 3)*2;
                *(float2*)&sc[r0*260 + c]     = make_float2(acc2[th][j][0], acc2[th][j][1]);
                *(float2*)&sc[(r0+8)*260 + c] = make_float2(acc2[th][j][2], acc2[th][j][3]);
            }
    }
    __syncthreads();
    float* ob = out + (size_t)n*CD*HWD + hw0;
    for (int i = tid; i < CD*32; i += 256) {
        const int c = i >> 5, t = i & 31;
        ob[(size_t)c*HWD + t] = sc[t*260 + c];
    }
}

// ---------------------------------------------------------------------------
extern "C" void kernel_launch(void* const* d_in, const int* in_sizes, int n_in,
                              void* d_out, int out_size) {
    const float* x      = (const float*)d_in[0];
    const float* memory = (const float*)d_in[1];
    const float* w1     = (const float*)d_in[2];
    const float* b1     = (const float*)d_in[3];
    const float* w2     = (const float*)d_in[4];
    const float* b2     = (const float*)d_in[5];

    float* out    = (float*)d_out;
    float* attmap = out + (size_t)NIMG*CD*HWD;

    mem_mlp_kernel<<<512, 256>>>(memory, w1, b1, w2, b2);
    pack2_kernel<<<128, 256>>>();

    cudaFuncSetAttribute(fused_kernel, cudaFuncAttributeMaxDynamicSharedMemorySize, SMEM_SZ);
    fused_kernel<<<1024, 256, SMEM_SZ>>>(x, out, attmap);
}

// round 15
// speedup vs baseline: 1.3428x; 1.0651x over previous
#include <cuda_runtime.h>
#include <cuda_fp16.h>
#include <cstdint>
#include <math.h>

#define CD 256
#define MD 512
#define HWD 4096
#define NIMG 16
#define LAMBDA 0.0025f
#define SROW 514

// SMEM layout (bytes)
#define XA_HI  65792u      // x-hat hi [32 x 528B]; later att hi [32 x 1040B]
#define ATT_HI 65792u
#define RED_O  99584u      // 256 f32
#define INV_O  100608u     // 32 f32
#define SMEM_SZ 100736u

// Fragment-major B operands (fp16): one warp LDG = 32 contiguous lanes.
__device__ uint2 g_B1f[32768];   // [(mtile*16+kt)*32+lane] hi pairs
__device__ uint4 g_B2f[32768];   // [(ctile*32+kt)*32+lane] {hi,lo,hi,lo}
__device__ __half g_Mh[MD*CD], g_Ml[MD*CD];

__device__ __forceinline__ uint32_t smem_u32(const void* p) {
    uint32_t a;
    asm("{ .reg .u64 t; cvta.to.shared.u64 t, %1; cvt.u32.u64 %0, t; }" : "=r"(a) : "l"(p));
    return a;
}
#define LDSM4(r,a) asm volatile("ldmatrix.sync.aligned.m8n8.x4.shared.b16 {%0,%1,%2,%3},[%4];" \
    : "=r"((r)[0]),"=r"((r)[1]),"=r"((r)[2]),"=r"((r)[3]) : "r"(a))
#define MMA(d,a,bb) asm volatile( \
    "mma.sync.aligned.m16n8k16.row.col.f32.f16.f16.f32 {%0,%1,%2,%3},{%4,%5,%6,%7},{%8,%9},{%0,%1,%2,%3};" \
    : "+f"((d)[0]),"+f"((d)[1]),"+f"((d)[2]),"+f"((d)[3]) \
    : "r"((a)[0]),"r"((a)[1]),"r"((a)[2]),"r"((a)[3]),"r"((bb)[0]),"r"((bb)[1]))

__device__ __forceinline__ void pack_h(const float* v, char* hi) {
    uint4 h;
    __half2 h0 = __floats2half2_rn(v[0], v[1]), h1 = __floats2half2_rn(v[2], v[3]);
    __half2 h2 = __floats2half2_rn(v[4], v[5]), h3 = __floats2half2_rn(v[6], v[7]);
    h.x = *(uint32_t*)&h0; h.y = *(uint32_t*)&h1; h.z = *(uint32_t*)&h2; h.w = *(uint32_t*)&h3;
    *(uint4*)hi = h;
}

// ---------------- prologue: MLP (1 slot/block, 512 blocks, k-split L1) ----------------
__global__ __launch_bounds__(256)
void mem_mlp_kernel(const float* __restrict__ memory,
                    const float* __restrict__ w1, const float* __restrict__ b1,
                    const float* __restrict__ w2, const float* __restrict__ b2) {
    __shared__ float srow[CD], part[256], h[128], scr[CD];
    __shared__ float invs_s;
    __shared__ __half sh[CD];
    const int m = blockIdx.x, tid = threadIdx.x, lane = tid & 31;

    srow[tid] = memory[m*CD + tid];
    __syncthreads();

    {   // layer1 k-split: u = tid&127, half = tid>>7 sums 128 c's
        const int u = tid & 127, half = tid >> 7;
        float a = half ? 0.f : b1[u];
        const int c0 = half*128;
#pragma unroll 32
        for (int c = c0; c < c0 + 128; c++) a += srow[c] * w1[c*128 + u];
        part[tid] = a;
    }
    __syncthreads();
    if (tid < 128) h[tid] = fmaxf(part[tid] + part[tid + 128], 0.f);
    __syncthreads();

    float a2 = b2[tid];
#pragma unroll 32
    for (int j = 0; j < 128; j++) a2 += h[j] * w2[j*CD + tid];
    a2 = fmaxf(a2, 0.f);
    scr[tid] = a2*a2;
    __syncthreads();
    if (tid < 32) {
        float ss = 0.f;
#pragma unroll
        for (int k = 0; k < 8; k++) ss += scr[tid + 32*k];
#pragma unroll
        for (int o = 16; o > 0; o >>= 1) ss += __shfl_xor_sync(0xffffffffu, ss, o);
        if (lane == 0) invs_s = 1.f / fmaxf(sqrtf(ss), 1e-12f);
    }
    __syncthreads();
    {
        const float v = a2 * invs_s;
        __half hb = __float2half_rn(v);
        g_Mh[m*CD + tid] = hb;
        g_Ml[m*CD + tid] = __float2half_rn(v - __half2float(hb));
        sh[tid] = hb;
    }
    __syncthreads();
    if (tid < 64) {
        const int kt = tid >> 2, q = tid & 3;
        const int c0 = kt*16 + 2*q;
        __half2 hh0, hh1;
        hh0.x = sh[c0];     hh0.y = sh[c0+1];
        hh1.x = sh[c0+8];   hh1.y = sh[c0+9];
        g_B1f[((m >> 3)*16 + kt)*32 + (m & 7)*4 + q] =
            make_uint2(*(uint32_t*)&hh0, *(uint32_t*)&hh1);
    }
}

// B2f pack: flat idx == output index (ct*1024 + kt*32 + lane)
__global__ void pack2_kernel() {
    const int idx = blockIdx.x*256 + threadIdx.x;   // 32768
    const int lane = idx & 31, kt = (idx >> 5) & 31, ct = idx >> 10;
    const int c = ct*8 + (lane >> 2), q = lane & 3;
    const int p0 = kt*8 + q, p1 = p0 + 4;
    __half2 hh0, ll0, hh1, ll1;
    hh0.x = g_Mh[(2*p0)*CD + c];   hh0.y = g_Mh[(2*p0+1)*CD + c];
    ll0.x = g_Ml[(2*p0)*CD + c];   ll0.y = g_Ml[(2*p0+1)*CD + c];
    hh1.x = g_Mh[(2*p1)*CD + c];   hh1.y = g_Mh[(2*p1+1)*CD + c];
    ll1.x = g_Ml[(2*p1)*CD + c];   ll1.y = g_Ml[(2*p1+1)*CD + c];
    g_B2f[idx] = make_uint4(*(uint32_t*)&hh0, *(uint32_t*)&ll0,
                            *(uint32_t*)&hh1, *(uint32_t*)&ll1);
}

// ---------------- fused HMMA kernel: 32 tok/CTA, 2 CTA/SM, fp16 ----------------
__global__ __launch_bounds__(256, 2)
void fused_kernel(const float* __restrict__ x, float* __restrict__ out,
                  float* __restrict__ attmap) {
    extern __shared__ char smem[];
    float* sc  = (float*)smem;
    float* red = (float*)(smem + RED_O);
    float* inv = (float*)(smem + INV_O);
    const uint32_t sb = smem_u32(smem);
    const int tid = threadIdx.x, lane = tid & 31, wid = tid >> 5;
    const int b = blockIdx.x;
    const int n = b >> 7;
    const int hw0 = (b & 127) << 5;
    const float* xb = x + (size_t)n*CD*HWD + hw0;

    // ---- stage x tile [256 c][32 t], coalesced ----
    for (int i = tid; i < CD*32; i += 256)
        sc[i] = xb[(size_t)(i >> 5)*HWD + (i & 31)];
    __syncthreads();

    // ---- token L2 norms ----
    {
        const int t = tid & 31, p = tid >> 5;
        float s = 0.f;
        for (int c = p*32; c < p*32 + 32; c++) { float v = sc[c*32 + t]; s += v*v; }
        red[p*32 + t] = s;
    }
    __syncthreads();
    if (tid < 32) {
        float s = 0.f;
        for (int p = 0; p < 8; p++) s += red[p*32 + tid];
        inv[tid] = 1.f / fmaxf(sqrtf(s), 1e-12f);
    }
    __syncthreads();

    // ---- pack x-hat hi tile [32 t][256 c], rows 528B (fp16 hi only) ----
    for (int i = tid; i < 1024; i += 256) {
        const int t = i >> 5, ch = i & 31;
        const float iv = inv[t];
        float v[8];
#pragma unroll
        for (int j = 0; j < 8; j++) v[j] = sc[(ch*8 + j)*32 + t] * iv;
        pack_h(v, smem + XA_HI + t*528 + ch*16);
    }
    __syncthreads();

    // ---- GEMM1: warp = 32 tok x 64 m, K=256, fp16 hi-only ----
    {
        const int mg = wid;
        float acc[2][8][4] = {};
        const uint32_t a0 = sb + XA_HI + (lane & 15)*528 + (lane >> 4)*16;
        const uint32_t a1 = a0 + 16*528;
        const uint2* b1p = g_B1f + (size_t)mg*8*512 + lane;
        uint2 qa[4], qb[4];
        uint32_t ah0[4], ah1[4];

#define G1LOAD(q, kt, JJ) { _Pragma("unroll") for (int j = 0; j < 4; j++) \
        (q)[j] = b1p[(size_t)((JJ)*4 + j)*512 + (kt)*32]; }
#define G1MMA(q, JJ) { _Pragma("unroll") for (int j = 0; j < 4; j++) { \
        uint32_t bh[2] = {(q)[j].x, (q)[j].y}; \
        MMA(acc[0][(JJ)*4+j], ah0, bh); MMA(acc[1][(JJ)*4+j], ah1, bh); } }

        G1LOAD(qa, 0, 0);
        for (int kt = 0; kt < 16; kt++) {
            LDSM4(ah0, a0 + kt*32);
            LDSM4(ah1, a1 + kt*32);
            G1LOAD(qb, kt, 1);
            G1MMA(qa, 0);
            if (kt < 15) G1LOAD(qa, kt+1, 0);
            G1MMA(qb, 1);
        }
#pragma unroll
        for (int th = 0; th < 2; th++)
#pragma unroll
            for (int j = 0; j < 8; j++) {
                const int r0 = th*16 + (lane >> 2);
                const int c = mg*64 + j*8 + (lane & 3)*2;
                *(float2*)&sc[r0*SROW + c]     = make_float2(acc[th][j][0], acc[th][j][1]);
                *(float2*)&sc[(r0+8)*SROW + c] = make_float2(acc[th][j][2], acc[th][j][3]);
            }
    }
    __syncthreads();

    // ---- softmax + shrink + L1 renorm (warp -> 4 tokens) ----
    for (int rt = 0; rt < 4; rt++) {
        const int t = wid*4 + rt;
        float* row = sc + t*SROW;
        float e[16], s = 0.f;
#pragma unroll
        for (int k = 0; k < 16; k++) { e[k] = __expf(row[lane + 32*k]); s += e[k]; }
#pragma unroll
        for (int o = 16; o > 0; o >>= 1) s += __shfl_xor_sync(0xffffffffu, s, o);
        const float invs = 1.f / s;
        float as = 0.f;
#pragma unroll
        for (int k = 0; k < 16; k++) { e[k] = fmaxf(e[k]*invs - LAMBDA, 0.f); as += e[k]; }
#pragma unroll
        for (int o = 16; o > 0; o >>= 1) as += __shfl_xor_sync(0xffffffffu, as, o);
        const float inva = 1.f / fmaxf(as, 1e-12f);
#pragma unroll
        for (int k = 0; k < 16; k++) row[lane + 32*k] = e[k] * inva;
    }
    __syncthreads();

    // ---- attmap write (coalesced along t) ----
    float* amb = attmap + (size_t)n*MD*HWD + hw0;
    for (int i = tid; i < MD*32; i += 256) {
        const int m = i >> 5, t = i & 31;
        amb[(size_t)m*HWD + t] = sc[t*SROW + m];
    }
    // reg-staged att pack (fp16 hi only): thread -> row pt, col block pg
    {
        const int pt = tid & 31, pg = (tid >> 5) * 64;
        float rbuf[64];
#pragma unroll
        for (int j = 0; j < 32; j++)
            *(float2*)&rbuf[2*j] = *(float2*)&sc[pt*SROW + pg + 2*j];
        __syncthreads();
        char* hb = smem + ATT_HI + pt*1040 + pg*2;
#pragma unroll
        for (int jg = 0; jg < 8; jg++)
            pack_h(rbuf + jg*8, hb + jg*16);
    }
    __syncthreads();

    // ---- GEMM2: warp = 32 tok x 32 c, K=512, fp16 att-hi x (m-hi + m-lo) ----
    float acc2[2][4][4] = {};
    {
        const int cg = wid;
        const uint4* b2p = g_B2f + (size_t)cg*4096 + lane;
        uint4 qa2[2], qb2[2];
        uint32_t ah[2][4];
        const uint32_t ha0 = sb + ATT_HI + (lane & 15)*1040 + (lane >> 4)*16;

#define G2LOAD(q, kt, JJ) { _Pragma("unroll") for (int j = 0; j < 2; j++) \
        (q)[j] = b2p[(size_t)((JJ)*2 + j)*1024 + (kt)*32]; }
#define G2MMA(q, JJ) { _Pragma("unroll") for (int j = 0; j < 2; j++) { \
        uint32_t bh[2] = {(q)[j].x, (q)[j].z}; \
        uint32_t bl[2] = {(q)[j].y, (q)[j].w}; \
        MMA(acc2[0][(JJ)*2+j], ah[0], bh); MMA(acc2[0][(JJ)*2+j], ah[0], bl); \
        MMA(acc2[1][(JJ)*2+j], ah[1], bh); MMA(acc2[1][(JJ)*2+j], ah[1], bl); } }

        G2LOAD(qa2, 0, 0);
        for (int kt = 0; kt < 32; kt++) {
            LDSM4(ah[0], ha0 + kt*32);
            LDSM4(ah[1], ha0 + 16*1040 + kt*32);
            G2LOAD(qb2, kt, 1);
            G2MMA(qa2, 0);
            if (kt < 31) G2LOAD(qa2, kt+1, 0);
            G2MMA(qb2, 1);
        }
    }
    __syncthreads();   // all warps done reading att tiles

    // ---- stage out [32 t][260], then coalesced write ----
    {
        const int cg = wid;
#pragma unroll
        for (int th = 0; th < 2; th++)
#pragma unroll
            for (int j = 0; j < 4; j++) {
                const int r0 = th*16 + (lane >> 2);
                const int c = cg*32 + j*8 + (lane & 3)*2;
                *(float2*)&sc[r0*260 + c]     = make_float2(acc2[th][j][0], acc2[th][j][1]);
                *(float2*)&sc[(r0+8)*260 + c] = make_float2(acc2[th][j][2], acc2[th][j][3]);
            }
    }
    __syncthreads();
    float* ob = out + (size_t)n*CD*HWD + hw0;
    for (int i = tid; i < CD*32; i += 256) {
        const int c = i >> 5, t = i & 31;
        ob[(size_t)c*HWD + t] = sc[t*260 + c];
    }
}

// ---------------------------------------------------------------------------
extern "C" void kernel_launch(void* const* d_in, const int* in_sizes, int n_in,
                              void* d_out, int out_size) {
    const float* x      = (const float*)d_in[0];
    const float* memory = (const float*)d_in[1];
    const float* w1     = (const float*)d_in[2];
    const float* b1     = (const float*)d_in[3];
    const float* w2     = (const float*)d_in[4];
    const float* b2     = (const float*)d_in[5];

    float* out    = (float*)d_out;
    float* attmap = out + (size_t)NIMG*CD*HWD;

    mem_mlp_kernel<<<512, 256>>>(memory, w1, b1, w2, b2);
    pack2_kernel<<<128, 256>>>();

    cudaFuncSetAttribute(fused_kernel, cudaFuncAttributeMaxDynamicSharedMemorySize, SMEM_SZ);
    fused_kernel<<<1024, 256, SMEM_SZ>>>(x, out, attmap);
}

// round 16
// speedup vs baseline: 1.5665x; 1.1666x over previous
#include <cuda_runtime.h>
#include <cuda_fp16.h>
#include <cstdint>
#include <math.h>

#define CD 256
#define MD 512
#define HWD 4096
#define NIMG 16
#define LAMBDA 0.0025f
#define SROW 514

// SMEM layout (bytes)
#define XA_HI  65792u      // x-hat hi [32 x 528B]; later att hi [32 x 1040B]
#define ATT_HI 65792u
#define RED_O  99584u      // 256 f32
#define INV_O  100608u     // 32 f32
#define SMEM_SZ 100736u

// Fragment-major B operands (fp16 hi-only): one warp LDG = 32 contiguous lanes.
__device__ uint2 g_B1f[32768];   // [(mtile*16+kt)*32+lane] hi pairs (c-pairs)
__device__ uint2 g_B2f[32768];   // [(ctile*32+kt)*32+lane] {hi(p0), hi(p1)}
__device__ __half g_Mh[MD*CD];

__device__ __forceinline__ uint32_t smem_u32(const void* p) {
    uint32_t a;
    asm("{ .reg .u64 t; cvta.to.shared.u64 t, %1; cvt.u32.u64 %0, t; }" : "=r"(a) : "l"(p));
    return a;
}
#define LDSM4(r,a) asm volatile("ldmatrix.sync.aligned.m8n8.x4.shared.b16 {%0,%1,%2,%3},[%4];" \
    : "=r"((r)[0]),"=r"((r)[1]),"=r"((r)[2]),"=r"((r)[3]) : "r"(a))
#define MMA(d,a,bb) asm volatile( \
    "mma.sync.aligned.m16n8k16.row.col.f32.f16.f16.f32 {%0,%1,%2,%3},{%4,%5,%6,%7},{%8,%9},{%0,%1,%2,%3};" \
    : "+f"((d)[0]),"+f"((d)[1]),"+f"((d)[2]),"+f"((d)[3]) \
    : "r"((a)[0]),"r"((a)[1]),"r"((a)[2]),"r"((a)[3]),"r"((bb)[0]),"r"((bb)[1]))

__device__ __forceinline__ void pack_h(const float* v, char* hi) {
    uint4 h;
    __half2 h0 = __floats2half2_rn(v[0], v[1]), h1 = __floats2half2_rn(v[2], v[3]);
    __half2 h2 = __floats2half2_rn(v[4], v[5]), h3 = __floats2half2_rn(v[6], v[7]);
    h.x = *(uint32_t*)&h0; h.y = *(uint32_t*)&h1; h.z = *(uint32_t*)&h2; h.w = *(uint32_t*)&h3;
    *(uint4*)hi = h;
}

// ---------------- prologue: MLP (1 slot/block, 512 blocks, 512 thr, deep k-split) ----------------
__global__ __launch_bounds__(512)
void mem_mlp_kernel(const float* __restrict__ memory,
                    const float* __restrict__ w1, const float* __restrict__ b1,
                    const float* __restrict__ w2, const float* __restrict__ b2) {
    __shared__ float srow[CD], part[512], h[128], scr[CD];
    __shared__ float invs_s;
    __shared__ __half sh[CD];
    const int m = blockIdx.x, tid = threadIdx.x, lane = tid & 31;

    if (tid < 256) srow[tid] = memory[m*CD + tid];
    __syncthreads();

    {   // layer1: unit u, quarter qr sums 64 c's
        const int u = tid & 127, qr = tid >> 7;
        float a = (qr == 0) ? b1[u] : 0.f;
        const int c0 = qr*64;
#pragma unroll 32
        for (int c = c0; c < c0 + 64; c++) a += srow[c] * w1[c*128 + u];
        part[tid] = a;
    }
    __syncthreads();
    if (tid < 128)
        h[tid] = fmaxf(part[tid] + part[tid+128] + part[tid+256] + part[tid+384], 0.f);
    __syncthreads();

    {   // layer2: channel c, half hf sums 64 j's
        const int c = tid & 255, hf = tid >> 8;
        float a = 0.f;
        const int j0 = hf*64;
#pragma unroll 32
        for (int j = j0; j < j0 + 64; j++) a += h[j] * w2[j*CD + c];
        part[tid] = a;
    }
    __syncthreads();
    float a2 = 0.f;
    if (tid < 256) {
        a2 = fmaxf(b2[tid] + part[tid] + part[tid+256], 0.f);
        scr[tid] = a2*a2;
    }
    __syncthreads();
    if (tid < 32) {
        float ss = 0.f;
#pragma unroll
        for (int k = 0; k < 8; k++) ss += scr[tid + 32*k];
#pragma unroll
        for (int o = 16; o > 0; o >>= 1) ss += __shfl_xor_sync(0xffffffffu, ss, o);
        if (lane == 0) invs_s = 1.f / fmaxf(sqrtf(ss), 1e-12f);
    }
    __syncthreads();
    if (tid < 256) {
        const __half hb = __float2half_rn(a2 * invs_s);
        g_Mh[m*CD + tid] = hb;
        sh[tid] = hb;
    }
    __syncthreads();
    if (tid < 64) {
        const int kt = tid >> 2, q = tid & 3;
        const int c0 = kt*16 + 2*q;
        __half2 hh0, hh1;
        hh0.x = sh[c0];     hh0.y = sh[c0+1];
        hh1.x = sh[c0+8];   hh1.y = sh[c0+9];
        g_B1f[((m >> 3)*16 + kt)*32 + (m & 7)*4 + q] =
            make_uint2(*(uint32_t*)&hh0, *(uint32_t*)&hh1);
    }
}

// B2f pack: flat idx == output index (ct*1024 + kt*32 + lane)
__global__ void pack2_kernel() {
    const int idx = blockIdx.x*256 + threadIdx.x;   // 32768
    const int lane = idx & 31, kt = (idx >> 5) & 31, ct = idx >> 10;
    const int c = ct*8 + (lane >> 2), q = lane & 3;
    const int p0 = kt*8 + q, p1 = p0 + 4;
    __half2 hh0, hh1;
    hh0.x = g_Mh[(2*p0)*CD + c];   hh0.y = g_Mh[(2*p0+1)*CD + c];
    hh1.x = g_Mh[(2*p1)*CD + c];   hh1.y = g_Mh[(2*p1+1)*CD + c];
    g_B2f[idx] = make_uint2(*(uint32_t*)&hh0, *(uint32_t*)&hh1);
}

// ---------------- fused HMMA kernel: 32 tok/CTA, 2 CTA/SM, fp16 hi-only ----------------
__global__ __launch_bounds__(256, 2)
void fused_kernel(const float* __restrict__ x, float* __restrict__ out,
                  float* __restrict__ attmap) {
    extern __shared__ char smem[];
    float* sc  = (float*)smem;
    float* red = (float*)(smem + RED_O);
    float* inv = (float*)(smem + INV_O);
    const uint32_t sb = smem_u32(smem);
    const int tid = threadIdx.x, lane = tid & 31, wid = tid >> 5;
    const int b = blockIdx.x;
    const int n = b >> 7;
    const int hw0 = (b & 127) << 5;
    const float* xb = x + (size_t)n*CD*HWD + hw0;

    // ---- stage x tile [256 c][32 t], coalesced ----
    for (int i = tid; i < CD*32; i += 256)
        sc[i] = xb[(size_t)(i >> 5)*HWD + (i & 31)];
    __syncthreads();

    // ---- token L2 norms ----
    {
        const int t = tid & 31, p = tid >> 5;
        float s = 0.f;
        for (int c = p*32; c < p*32 + 32; c++) { float v = sc[c*32 + t]; s += v*v; }
        red[p*32 + t] = s;
    }
    __syncthreads();
    if (tid < 32) {
        float s = 0.f;
        for (int p = 0; p < 8; p++) s += red[p*32 + tid];
        inv[tid] = 1.f / fmaxf(sqrtf(s), 1e-12f);
    }
    __syncthreads();

    // ---- pack x-hat hi tile [32 t][256 c], rows 528B (fp16 hi only) ----
    for (int i = tid; i < 1024; i += 256) {
        const int t = i >> 5, ch = i & 31;
        const float iv = inv[t];
        float v[8];
#pragma unroll
        for (int j = 0; j < 8; j++) v[j] = sc[(ch*8 + j)*32 + t] * iv;
        pack_h(v, smem + XA_HI + t*528 + ch*16);
    }
    __syncthreads();

    // ---- GEMM1: warp = 32 tok x 64 m, K=256, fp16 hi-only ----
    {
        const int mg = wid;
        float acc[2][8][4] = {};
        const uint32_t a0 = sb + XA_HI + (lane & 15)*528 + (lane >> 4)*16;
        const uint32_t a1 = a0 + 16*528;
        const uint2* b1p = g_B1f + (size_t)mg*8*512 + lane;
        uint2 qa[4], qb[4];
        uint32_t ah0[4], ah1[4];

#define G1LOAD(q, kt, JJ) { _Pragma("unroll") for (int j = 0; j < 4; j++) \
        (q)[j] = b1p[(size_t)((JJ)*4 + j)*512 + (kt)*32]; }
#define G1MMA(q, JJ) { _Pragma("unroll") for (int j = 0; j < 4; j++) { \
        uint32_t bh[2] = {(q)[j].x, (q)[j].y}; \
        MMA(acc[0][(JJ)*4+j], ah0, bh); MMA(acc[1][(JJ)*4+j], ah1, bh); } }

        G1LOAD(qa, 0, 0);
        for (int kt = 0; kt < 16; kt++) {
            LDSM4(ah0, a0 + kt*32);
            LDSM4(ah1, a1 + kt*32);
            G1LOAD(qb, kt, 1);
            G1MMA(qa, 0);
            if (kt < 15) G1LOAD(qa, kt+1, 0);
            G1MMA(qb, 1);
        }
#pragma unroll
        for (int th = 0; th < 2; th++)
#pragma unroll
            for (int j = 0; j < 8; j++) {
                const int r0 = th*16 + (lane >> 2);
                const int c = mg*64 + j*8 + (lane & 3)*2;
                *(float2*)&sc[r0*SROW + c]     = make_float2(acc[th][j][0], acc[th][j][1]);
                *(float2*)&sc[(r0+8)*SROW + c] = make_float2(acc[th][j][2], acc[th][j][3]);
            }
    }
    __syncthreads();

    // ---- softmax + shrink + L1 renorm (warp -> 4 tokens) ----
    for (int rt = 0; rt < 4; rt++) {
        const int t = wid*4 + rt;
        float* row = sc + t*SROW;
        float e[16], s = 0.f;
#pragma unroll
        for (int k = 0; k < 16; k++) { e[k] = __expf(row[lane + 32*k]); s += e[k]; }
#pragma unroll
        for (int o = 16; o > 0; o >>= 1) s += __shfl_xor_sync(0xffffffffu, s, o);
        const float invs = 1.f / s;
        float as = 0.f;
#pragma unroll
        for (int k = 0; k < 16; k++) { e[k] = fmaxf(e[k]*invs - LAMBDA, 0.f); as += e[k]; }
#pragma unroll
        for (int o = 16; o > 0; o >>= 1) as += __shfl_xor_sync(0xffffffffu, as, o);
        const float inva = 1.f / fmaxf(as, 1e-12f);
#pragma unroll
        for (int k = 0; k < 16; k++) row[lane + 32*k] = e[k] * inva;
    }
    __syncthreads();

    // ---- attmap write (coalesced along t) ----
    float* amb = attmap + (size_t)n*MD*HWD + hw0;
    for (int i = tid; i < MD*32; i += 256) {
        const int m = i >> 5, t = i & 31;
        amb[(size_t)m*HWD + t] = sc[t*SROW + m];
    }
    // reg-staged att pack (fp16 hi only): thread -> row pt, col block pg
    {
        const int pt = tid & 31, pg = (tid >> 5) * 64;
        float rbuf[64];
#pragma unroll
        for (int j = 0; j < 32; j++)
            *(float2*)&rbuf[2*j] = *(float2*)&sc[pt*SROW + pg + 2*j];
        __syncthreads();
        char* hb = smem + ATT_HI + pt*1040 + pg*2;
#pragma unroll
        for (int jg = 0; jg < 8; jg++)
            pack_h(rbuf + jg*8, hb + jg*16);
    }
    __syncthreads();

    // ---- GEMM2: warp = 32 tok x 32 c, K=512, fp16 hi x hi ----
    float acc2[2][4][4] = {};
    {
        const int cg = wid;
        const uint2* b2p = g_B2f + (size_t)cg*4096 + lane;
        uint2 qa2[2], qb2[2];
        uint32_t ah[2][4];
        const uint32_t ha0 = sb + ATT_HI + (lane & 15)*1040 + (lane >> 4)*16;

#define G2LOAD(q, kt, JJ) { _Pragma("unroll") for (int j = 0; j < 2; j++) \
        (q)[j] = b2p[(size_t)((JJ)*2 + j)*1024 + (kt)*32]; }
#define G2MMA(q, JJ) { _Pragma("unroll") for (int j = 0; j < 2; j++) { \
        uint32_t bh[2] = {(q)[j].x, (q)[j].y}; \
        MMA(acc2[0][(JJ)*2+j], ah[0], bh); \
        MMA(acc2[1][(JJ)*2+j], ah[1], bh); } }

        G2LOAD(qa2, 0, 0);
        for (int kt = 0; kt < 32; kt++) {
            LDSM4(ah[0], ha0 + kt*32);
            LDSM4(ah[1], ha0 + 16*1040 + kt*32);
            G2LOAD(qb2, kt, 1);
            G2MMA(qa2, 0);
            if (kt < 31) G2LOAD(qa2, kt+1, 0);
            G2MMA(qb2, 1);
        }
    }
    __syncthreads();   // all warps done reading att tiles

    // ---- stage out [32 t][260], then coalesced write ----
    {
        const int cg = wid;
#pragma unroll
        for (int th = 0; th < 2; th++)
#pragma unroll
            for (int j = 0; j < 4; j++) {
                const int r0 = th*16 + (lane >> 2);
                const int c = cg*32 + j*8 + (lane & 3)*2;
                *(float2*)&sc[r0*260 + c]     = make_float2(acc2[th][j][0], acc2[th][j][1]);
                *(float2*)&sc[(r0+8)*260 + c] = make_float2(acc2[th][j][2], acc2[th][j][3]);
            }
    }
    __syncthreads();
    float* ob = out + (size_t)n*CD*HWD + hw0;
    for (int i = tid; i < CD*32; i += 256) {
        const int c = i >> 5, t = i & 31;
        ob[(size_t)c*HWD + t] = sc[t*260 + c];
    }
}

// ---------------------------------------------------------------------------
extern "C" void kernel_launch(void* const* d_in, const int* in_sizes, int n_in,
                              void* d_out, int out_size) {
    const float* x      = (const float*)d_in[0];
    const float* memory = (const float*)d_in[1];
    const float* w1     = (const float*)d_in[2];
    const float* b1     = (const float*)d_in[3];
    const float* w2     = (const float*)d_in[4];
    const float* b2     = (const float*)d_in[5];

    float* out    = (float*)d_out;
    float* attmap = out + (size_t)NIMG*CD*HWD;

    mem_mlp_kernel<<<512, 512>>>(memory, w1, b1, w2, b2);
    pack2_kernel<<<128, 256>>>();

    cudaFuncSetAttribute(fused_kernel, cudaFuncAttributeMaxDynamicSharedMemorySize, SMEM_SZ);
    fused_kernel<<<1024, 256, SMEM_SZ>>>(x, out, attmap);
}